// round 8
// baseline (speedup 1.0000x reference)
#include <cuda_runtime.h>
#include <math.h>

#define N_ROWS   16384
#define ACTIONS  64
#define EMB      32
#define DELTA    16
#define EPSF     1e-5f

#define NB1      32                      // bn_partial blocks
#define ROWS_PER_B1 (N_ROWS / NB1)       // 512

#define GRID2    1024                    // spline blocks
#define ROWS_PER_B2 (N_ROWS / GRID2)     // 16
#define CHUNK_ROWS  4                    // rows per TMA store chunk
#define NCHUNK   (ROWS_PER_B2 / CHUNK_ROWS)          // 4
#define CHUNK_BYTES (CHUNK_ROWS * ACTIONS * EMB * 4) // 32768
#define CHUNK_F4    (CHUNK_BYTES / 16)               // 2048
#define SMEM_DYN_BYTES (2 * CHUNK_BYTES)             // 65536 (double buffer)

// Scratch: BN partial sums (no allocation allowed in kernel_launch).
__device__ float g_psum[NB1][ACTIONS];
__device__ float g_psq [NB1][ACTIONS];

__device__ __forceinline__ unsigned smem_u32(const void* p) {
    unsigned a;
    asm("{ .reg .u64 t; cvta.to.shared.u64 t, %1; cvt.u32.u64 %0, t; }"
        : "=r"(a) : "l"(p));
    return a;
}

// ---------------------------------------------------------------------------
// Kernel 1: per-block partial sum/sumsq per action column. 32 blocks x 512
// rows. float4 loads in explicit 8-deep batches (MLP=8). Deterministic.
// ---------------------------------------------------------------------------
__global__ __launch_bounds__(256) void bn_partial(const float* __restrict__ x)
{
    const int tid = threadIdx.x;
    const int c4  = tid & 15;
    const int r   = tid >> 4;
    const int b   = blockIdx.x;

    const float4* px = reinterpret_cast<const float4*>(x)
                     + (size_t)(b * ROWS_PER_B1 + r) * (ACTIONS / 4) + c4;

    float4 s = {0.f, 0.f, 0.f, 0.f};
    float4 q = {0.f, 0.f, 0.f, 0.f};
#pragma unroll
    for (int m = 0; m < 4; m++) {
        float4 v[8];
#pragma unroll
        for (int k = 0; k < 8; k++)
            v[k] = __ldg(px + (size_t)(m * 8 + k) * 16 * (ACTIONS / 4));
#pragma unroll
        for (int k = 0; k < 8; k++) {
            s.x += v[k].x; q.x += v[k].x * v[k].x;
            s.y += v[k].y; q.y += v[k].y * v[k].y;
            s.z += v[k].z; q.z += v[k].z * v[k].z;
            s.w += v[k].w; q.w += v[k].w * v[k].w;
        }
    }

    __shared__ float4 ss[16][16];
    __shared__ float4 sq[16][16];
    ss[r][c4] = s;
    sq[r][c4] = q;
    __syncthreads();

    if (tid < ACTIONS) {
        const int c = tid, cc = c >> 2, ce = c & 3;
        float ts = 0.f, tq = 0.f;
#pragma unroll
        for (int r2 = 0; r2 < 16; r2++) {
            ts += reinterpret_cast<const float*>(&ss[r2][cc])[ce];
            tq += reinterpret_cast<const float*>(&sq[r2][cc])[ce];
        }
        g_psum[b][c] = ts;
        g_psq [b][c] = tq;
    }
}

// ---------------------------------------------------------------------------
// Kernel 2 (fused): BN finalize prologue + spline, TMA bulk-store output.
//  - Block: 256 threads, 16 rows, processed as 4 chunks of (4 rows x 64 act).
//  - Warp = (1 row, 32 actions): x-load is one contiguous 128B LDG; tanh on
//    ALL 32 lanes (one pair per lane), results broadcast per-iter via shfl.
//  - Inner iter: warp covers 4 pairs (8 lanes each); 2 gather LDG.128
//    (table rows are exactly one 128B line each; bh row = bl row + 64);
//    lerp; STS.128 of contiguous 512B into the smem chunk buffer.
//  - Chunk epilogue: cp.async.bulk.global.shared::cta moves 32KB smem->gmem
//    on the bulk-copy engine, bypassing the per-instruction STG cost that
//    made the previous kernel l1tex-bound (77% L1, 12cyc/STG.128).
//    Double-buffered; wait_group.read 1 guards buffer reuse; store of chunk
//    c overlaps compute of chunk c+1.
//  - Deterministic: fixed-order reductions, bit-identical prologue per block.
// ---------------------------------------------------------------------------
__global__ __launch_bounds__(256) void spline_tma(const float* __restrict__ x,
                                                  const float* __restrict__ emb,
                                                  const float* __restrict__ wgt,
                                                  const float* __restrict__ bias,
                                                  float* __restrict__ out)
{
    extern __shared__ float4 buf[];          // [2][CHUNK_F4]
    __shared__ float s_sc[ACTIONS];
    __shared__ float s_sh[ACTIONS];

    const int tid = threadIdx.x;

    // ---- BN finalize prologue: reduce 32 partials per action ----
    {
        const int c = tid & 63;
        const int q = tid >> 6;              // 0..3
        float s = 0.f, qq = 0.f;
#pragma unroll
        for (int i = 0; i < 8; i++) {
            s  += g_psum[q * 8 + i][c];
            qq += g_psq [q * 8 + i][c];
        }
        float* scratch = reinterpret_cast<float*>(buf);   // 512 floats
        scratch[q * 64 + c]       = s;
        scratch[256 + q * 64 + c] = qq;
        __syncthreads();
        if (tid < ACTIONS) {
            float ts = ((scratch[c] + scratch[64 + c]) + scratch[128 + c]) + scratch[192 + c];
            float tq = ((scratch[256 + c] + scratch[320 + c]) + scratch[384 + c]) + scratch[448 + c];
            const float inv_n = 1.0f / (float)N_ROWS;
            float mean = ts * inv_n;
            float var  = fmaf(-mean, mean, tq * inv_n);
            float sc   = wgt[tid] * rsqrtf(var + EPSF);
            s_sc[tid] = sc;
            s_sh[tid] = fmaf(-mean, sc, bias[tid]);
        }
        __syncthreads();
    }

    const int lane    = tid & 31;
    const int w       = tid >> 5;            // warp 0..7
    const int lane8   = lane & 7;
    const int g       = lane >> 3;           // pair-in-group 0..3
    const int r_local = w >> 1;              // row within chunk 0..3
    const int ahalf   = (w & 1) * 32;        // action half
    const int my_a    = ahalf + lane;        // this lane's action

    const float sc = s_sc[my_a];
    const float sh = s_sh[my_a];

    const int row0 = blockIdx.x * ROWS_PER_B2;
    const float4* emb4 = reinterpret_cast<const float4*>(emb);
    const unsigned sbase = smem_u32(buf);

    for (int ch = 0; ch < NCHUNK; ch++) {
        // Ensure the target buffer's previous bulk store has drained.
        if (tid == 0)
            asm volatile("cp.async.bulk.wait_group.read 1;" ::: "memory");
        __syncthreads();

        const int grow = row0 + ch * CHUNK_ROWS + r_local;

        // One pair per lane: coalesced 128B x-load, full-lane tanh.
        const float xv = __ldg(x + (size_t)grow * ACTIONS + my_a);
        float t = tanhf(fmaf(xv, sc, sh));
        t = fminf(fmaxf(t, -1.0f + 1e-5f), 1.0f - 1e-5f);
        const float f   = t * (float)DELTA;          // exact pow2 scale
        const float xlf = floorf(f);
        const float wh_all = f - xlf;                // DELTA*(t-xl), exact
        const int   li_all = (((int)xlf) + DELTA) * ACTIONS + my_a;

        float4* cbuf = buf + (ch & 1) * CHUNK_F4
                     + (size_t)(r_local * ACTIONS + ahalf) * (EMB / 4);

#pragma unroll
        for (int j = 0; j < 8; j++) {
            const float wh = __shfl_sync(0xffffffffu, wh_all, j * 4 + g);
            const int   li = __shfl_sync(0xffffffffu, li_all, j * 4 + g);
            const float wl = 1.0f - wh;

            const float4* bl4 = emb4 + (size_t)li * (EMB / 4) + lane8;
            const float4 bl = __ldg(bl4);
            const float4 bh = __ldg(bl4 + ACTIONS * (EMB / 4));   // row+64

            float4 h;
            h.x = bh.x * wh + bl.x * wl;
            h.y = bh.y * wh + bl.y * wl;
            h.z = bh.z * wh + bl.z * wl;
            h.w = bh.w * wh + bl.w * wl;

            // contiguous 512B per warp-iter: actions jb..jb+3, all 8 f4 slots
            cbuf[(size_t)(j * 4 + g) * (EMB / 4) + lane8] = h;
        }

        // Make generic-proxy smem writes visible to the async proxy.
        asm volatile("fence.proxy.async.shared::cta;" ::: "memory");
        __syncthreads();

        if (tid == 0) {
            char* gdst = reinterpret_cast<char*>(out)
                       + (size_t)(row0 + ch * CHUNK_ROWS) * ACTIONS * EMB * 4;
            const unsigned saddr = sbase + (unsigned)((ch & 1) * CHUNK_BYTES);
            asm volatile(
                "cp.async.bulk.global.shared::cta.bulk_group [%0], [%1], %2;"
                :: "l"(gdst), "r"(saddr), "r"(CHUNK_BYTES) : "memory");
            asm volatile("cp.async.bulk.commit_group;" ::: "memory");
        }
    }

    // Drain all outstanding bulk stores before exit.
    if (tid == 0)
        asm volatile("cp.async.bulk.wait_group 0;" ::: "memory");
}

// ---------------------------------------------------------------------------
// Launch: x, bn_weight, bn_bias, emb_table  ->  out [n, ACTIONS, EMB] fp32
// ---------------------------------------------------------------------------
extern "C" void kernel_launch(void* const* d_in, const int* in_sizes, int n_in,
                              void* d_out, int out_size)
{
    const float* x    = (const float*)d_in[0];
    const float* wgt  = (const float*)d_in[1];
    const float* bias = (const float*)d_in[2];
    const float* emb  = (const float*)d_in[3];
    float* out        = (float*)d_out;

    // Unconditional + idempotent (no static guards allowed): host-side
    // attribute set, creates no graph node, legal during capture.
    cudaFuncSetAttribute(spline_tma,
                         cudaFuncAttributeMaxDynamicSharedMemorySize,
                         SMEM_DYN_BYTES);

    bn_partial<<<NB1, 256>>>(x);
    spline_tma<<<GRID2, 256, SMEM_DYN_BYTES>>>(x, emb, wgt, bias, out);
}

// round 9
// speedup vs baseline: 1.3750x; 1.3750x over previous
#include <cuda_runtime.h>
#include <math.h>

#define N_ROWS   16384
#define ACTIONS  64
#define EMB      32
#define DELTA    16
#define EPSF     1e-5f

#define NB1      32                      // bn_partial blocks
#define ROWS_PER_B1 (N_ROWS / NB1)       // 512

#define A_PER_B  4                       // actions per spline block
#define R_PER_B  256                     // rows per spline block

// Scratch: BN partial sums (no allocation allowed in kernel_launch).
__device__ float g_psum[NB1][ACTIONS];
__device__ float g_psq [NB1][ACTIONS];

// ---------------------------------------------------------------------------
// Kernel 1: per-block partial sum/sumsq per action column. 32 blocks x 512
// rows. float4 loads in explicit 8-deep batches (MLP=8). Deterministic.
// ---------------------------------------------------------------------------
__global__ __launch_bounds__(256) void bn_partial(const float* __restrict__ x)
{
    const int tid = threadIdx.x;
    const int c4  = tid & 15;
    const int r   = tid >> 4;
    const int b   = blockIdx.x;

    const float4* px = reinterpret_cast<const float4*>(x)
                     + (size_t)(b * ROWS_PER_B1 + r) * (ACTIONS / 4) + c4;

    float4 s = {0.f, 0.f, 0.f, 0.f};
    float4 q = {0.f, 0.f, 0.f, 0.f};
#pragma unroll
    for (int m = 0; m < 4; m++) {
        float4 v[8];
#pragma unroll
        for (int k = 0; k < 8; k++)
            v[k] = __ldg(px + (size_t)(m * 8 + k) * 16 * (ACTIONS / 4));
#pragma unroll
        for (int k = 0; k < 8; k++) {
            s.x += v[k].x; q.x += v[k].x * v[k].x;
            s.y += v[k].y; q.y += v[k].y * v[k].y;
            s.z += v[k].z; q.z += v[k].z * v[k].z;
            s.w += v[k].w; q.w += v[k].w * v[k].w;
        }
    }

    __shared__ float4 ss[16][16];
    __shared__ float4 sq[16][16];
    ss[r][c4] = s;
    sq[r][c4] = q;
    __syncthreads();

    if (tid < ACTIONS) {
        const int c = tid, cc = c >> 2, ce = c & 3;
        float ts = 0.f, tq = 0.f;
#pragma unroll
        for (int r2 = 0; r2 < 16; r2++) {
            ts += reinterpret_cast<const float*>(&ss[r2][cc])[ce];
            tq += reinterpret_cast<const float*>(&sq[r2][cc])[ce];
        }
        g_psum[b][c] = ts;
        g_psq [b][c] = tq;
    }
}

// ---------------------------------------------------------------------------
// Kernel 2 (fused): BN-finalize prologue + spline. One-line-per-instruction
// memory design (kills the 2.07cyc/wf within-instruction replay that bound
// the previous STG.128 kernel at 77% l1tex):
//  - Block: 256 threads = 8 warps; covers 4 actions x 256 rows.
//    Table slice = 4 actions x 33 rows x 128B = 17KB -> L1-resident gathers.
//  - Warp: 32 rows x 4 actions. x: one float4/lane (row's 4 actions).
//    tanh once per pair, all 32 lanes busy.
//  - Per pair (one warp-iter): broadcast f=16*t via 1 shfl; gathers are
//    LDG.32 with 32 consecutive lanes = EXACTLY one 128B line each (table
//    row is 128B); store STG.32 = one line. 3 LSU ops/pair, 3 wavefronts,
//    no multi-line replay.
//  - bh row = bl row + 64 (xh = xl+1 always); wl = 1-wh exact (pow2 scale).
//  - Prologue: butterfly-reduce 32 partials for the block's 4 actions;
//    fixed lane pairing -> bit-identical scale/shift everywhere.
// ---------------------------------------------------------------------------
__global__ __launch_bounds__(256) void spline_v3(const float* __restrict__ x,
                                                 const float* __restrict__ emb,
                                                 const float* __restrict__ wgt,
                                                 const float* __restrict__ bias,
                                                 float* __restrict__ out)
{
    const int tid  = threadIdx.x;
    const int lane = tid & 31;
    const int w    = tid >> 5;                 // warp 0..7
    const int a0   = blockIdx.y * A_PER_B;     // first action of block
    const int row0 = blockIdx.x * R_PER_B + w * 32;

    // ---- BN finalize prologue: 4 actions x 32 partials, butterfly reduce ----
    __shared__ float s_sc[A_PER_B];
    __shared__ float s_sh[A_PER_B];
    if (tid < 128) {
        const int ai = tid >> 5;               // action index 0..3
        const int p  = tid & 31;               // partial index
        float s = g_psum[p][a0 + ai];
        float q = g_psq [p][a0 + ai];
#pragma unroll
        for (int off = 16; off > 0; off >>= 1) {
            s += __shfl_xor_sync(0xffffffffu, s, off);
            q += __shfl_xor_sync(0xffffffffu, q, off);
        }
        if (p == 0) {
            const float inv_n = 1.0f / (float)N_ROWS;
            float mean = s * inv_n;
            float var  = fmaf(-mean, mean, q * inv_n);   // E[x^2]-mean^2
            float sc   = wgt[a0 + ai] * rsqrtf(var + EPSF);
            s_sc[ai] = sc;
            s_sh[ai] = fmaf(-mean, sc, bias[a0 + ai]);
        }
    }
    __syncthreads();

    // ---- per-lane x load (one row's 4 actions) + 4 tanh ----
    const float4 xv = __ldg(reinterpret_cast<const float4*>(
                          x + (size_t)(row0 + lane) * ACTIONS + a0));
    float f[4];
    {
        const float xs[4] = {xv.x, xv.y, xv.z, xv.w};
#pragma unroll
        for (int q = 0; q < 4; q++) {
            float t = tanhf(fmaf(xs[q], s_sc[q], s_sh[q]));
            t = fminf(fmaxf(t, -1.0f + 1e-5f), 1.0f - 1e-5f);
            f[q] = t * (float)DELTA;           // exact pow2 scale; frac/floor below
        }
    }

    // ---- main loop: 128 pairs/warp, one pair per iter, 32 lanes each ----
    const float* embL = emb + lane;            // lane's emb element
    float*       outL = out + lane;

#pragma unroll 2
    for (int jb = 0; jb < 32; jb++) {
#pragma unroll
        for (int q = 0; q < A_PER_B; q++) {
            const float fj  = __shfl_sync(0xffffffffu, f[q], jb);
            const float xlf = floorf(fj);
            const float wh  = fj - xlf;        // = DELTA*(t-xl), exact
            const float wl  = 1.0f - wh;       // = DELTA*(xh-t)
            const int   li  = (((int)xlf) + DELTA) * ACTIONS + a0 + q;

            const float bl = __ldg(embL + (size_t)li * EMB);
            const float bh = __ldg(embL + (size_t)(li + ACTIONS) * EMB);

            const float h = bh * wh + bl * wl;

            __stcs(outL + ((size_t)(row0 + jb) * ACTIONS + a0 + q) * EMB, h);
        }
    }
}

// ---------------------------------------------------------------------------
// Launch: x, bn_weight, bn_bias, emb_table  ->  out [n, ACTIONS, EMB] fp32
// ---------------------------------------------------------------------------
extern "C" void kernel_launch(void* const* d_in, const int* in_sizes, int n_in,
                              void* d_out, int out_size)
{
    const float* x    = (const float*)d_in[0];
    const float* wgt  = (const float*)d_in[1];
    const float* bias = (const float*)d_in[2];
    const float* emb  = (const float*)d_in[3];
    float* out        = (float*)d_out;

    bn_partial<<<NB1, 256>>>(x);

    dim3 grid(N_ROWS / R_PER_B, ACTIONS / A_PER_B);   // (64, 16)
    spline_v3<<<grid, 256>>>(x, emb, wgt, bias, out);
}

// round 13
// speedup vs baseline: 1.5334x; 1.1152x over previous
#include <cuda_runtime.h>
#include <math.h>

#define N_ROWS   16384
#define ACTIONS  64
#define EMB      32
#define DELTA    16
#define EPSF     1e-5f

#define NB1      32                      // bn_partial blocks
#define ROWS_PER_B1 (N_ROWS / NB1)       // 512

#define A_PER_B  4                       // actions per spline block
#define R_PER_B  256                     // rows per spline block
#define NBINS    33                      // staged bins (bl 0..31, bh needs +1)

// Scratch: BN partial sums (no allocation allowed in kernel_launch).
__device__ float g_psum[NB1][ACTIONS];
__device__ float g_psq [NB1][ACTIONS];

// ---------------------------------------------------------------------------
// Kernel 1: per-block partial sum/sumsq per action column. 32 blocks x 512
// rows. float4 loads in explicit 8-deep batches (MLP=8). Deterministic.
// ---------------------------------------------------------------------------
__global__ __launch_bounds__(256) void bn_partial(const float* __restrict__ x)
{
    const int tid = threadIdx.x;
    const int c4  = tid & 15;
    const int r   = tid >> 4;
    const int b   = blockIdx.x;

    const float4* px = reinterpret_cast<const float4*>(x)
                     + (size_t)(b * ROWS_PER_B1 + r) * (ACTIONS / 4) + c4;

    float4 s = {0.f, 0.f, 0.f, 0.f};
    float4 q = {0.f, 0.f, 0.f, 0.f};
#pragma unroll
    for (int m = 0; m < 4; m++) {
        float4 v[8];
#pragma unroll
        for (int k = 0; k < 8; k++)
            v[k] = __ldg(px + (size_t)(m * 8 + k) * 16 * (ACTIONS / 4));
#pragma unroll
        for (int k = 0; k < 8; k++) {
            s.x += v[k].x; q.x += v[k].x * v[k].x;
            s.y += v[k].y; q.y += v[k].y * v[k].y;
            s.z += v[k].z; q.z += v[k].z * v[k].z;
            s.w += v[k].w; q.w += v[k].w * v[k].w;
        }
    }

    __shared__ float4 ss[16][16];
    __shared__ float4 sq[16][16];
    ss[r][c4] = s;
    sq[r][c4] = q;
    __syncthreads();

    if (tid < ACTIONS) {
        const int c = tid, cc = c >> 2, ce = c & 3;
        float ts = 0.f, tq = 0.f;
#pragma unroll
        for (int r2 = 0; r2 < 16; r2++) {
            ts += reinterpret_cast<const float*>(&ss[r2][cc])[ce];
            tq += reinterpret_cast<const float*>(&sq[r2][cc])[ce];
        }
        g_psum[b][c] = ts;
        g_psq [b][c] = tq;
    }
}

// ---------------------------------------------------------------------------
// Kernel 2 (fused): BN prologue + smem-staged spline.
// LSU-issue-floor design (v3 was AT its floor: 2 LDG.32 + STG.32 =
// 8.6 cyc/pair = 35us exactly):
//  - Table slice (33 bins x 4 actions x 128B = 16.9 KB) staged in smem once
//    per block; bh = bin+1 row of the SAME array (xh = xl+1 always).
//  - Warp-iter = one row's 4 actions (4 pairs): 2x LDS.128 (each 8-lane
//    group reads one aligned 128B table row -> conflict-free 4-phase) and
//    ONE STG.128 of 512B contiguous output -> store issue 12cyc/4 pairs
//    = 3 cyc/pair (was 5).
//  - Per-lane f values (4 actions per row, row = lane) broadcast with
//    4 shfl + 3 SEL (value-select by pair-group; no divergent reg indexing).
//  - Deterministic: fixed-order butterfly prologue, bit-identical per block.
// ---------------------------------------------------------------------------
__global__ __launch_bounds__(256) void spline_v4(const float* __restrict__ x,
                                                 const float* __restrict__ emb,
                                                 const float* __restrict__ wgt,
                                                 const float* __restrict__ bias,
                                                 float* __restrict__ out)
{
    __shared__ __align__(16) float s_tab[NBINS * A_PER_B * EMB]; // [bin][a][e]
    __shared__ float s_sc[A_PER_B];
    __shared__ float s_sh[A_PER_B];

    const int tid  = threadIdx.x;
    const int lane = tid & 31;
    const int w    = tid >> 5;                 // warp 0..7
    const int a0   = blockIdx.y * A_PER_B;
    const int row0 = blockIdx.x * R_PER_B + w * 32;

    // ---- BN finalize: 4 actions x 32 partials, butterfly reduce ----
    if (tid < 128) {
        const int ai = tid >> 5;
        const int p  = tid & 31;
        float s = g_psum[p][a0 + ai];
        float q = g_psq [p][a0 + ai];
#pragma unroll
        for (int off = 16; off > 0; off >>= 1) {
            s += __shfl_xor_sync(0xffffffffu, s, off);
            q += __shfl_xor_sync(0xffffffffu, q, off);
        }
        if (p == 0) {
            const float inv_n = 1.0f / (float)N_ROWS;
            float mean = s * inv_n;
            float var  = fmaf(-mean, mean, q * inv_n);
            float sc   = wgt[a0 + ai] * rsqrtf(var + EPSF);
            s_sc[ai] = sc;
            s_sh[ai] = fmaf(-mean, sc, bias[a0 + ai]);
        }
    }

    // ---- stage table slice: bins 0..32, this block's 4 actions ----
    {
        float4* st4 = reinterpret_cast<float4*>(s_tab);
        const float4* e4p = reinterpret_cast<const float4*>(emb);
        // 33*4*8 = 1056 float4
        for (int i = tid; i < NBINS * A_PER_B * 8; i += 256) {
            const int bin = i >> 5;            // /32
            const int a   = (i >> 3) & 3;
            const int e4  = i & 7;
            st4[i] = __ldg(e4p + ((size_t)bin * ACTIONS + a0 + a) * 8 + e4);
        }
    }
    __syncthreads();

    // ---- per-lane x load (row row0+lane, 4 actions) + 4 tanh ----
    const float4 xv = __ldg(reinterpret_cast<const float4*>(
                          x + (size_t)(row0 + lane) * ACTIONS + a0));
    float f0, f1, f2, f3;
    {
        float t;
        t = tanhf(fmaf(xv.x, s_sc[0], s_sh[0]));
        f0 = fminf(fmaxf(t, -1.0f + 1e-5f), 1.0f - 1e-5f) * (float)DELTA;
        t = tanhf(fmaf(xv.y, s_sc[1], s_sh[1]));
        f1 = fminf(fmaxf(t, -1.0f + 1e-5f), 1.0f - 1e-5f) * (float)DELTA;
        t = tanhf(fmaf(xv.z, s_sc[2], s_sh[2]));
        f2 = fminf(fmaxf(t, -1.0f + 1e-5f), 1.0f - 1e-5f) * (float)DELTA;
        t = tanhf(fmaf(xv.w, s_sc[3], s_sh[3]));
        f3 = fminf(fmaxf(t, -1.0f + 1e-5f), 1.0f - 1e-5f) * (float)DELTA;
    }

    const int g  = lane >> 3;                  // pair group 0..3 (action)
    const int e4 = lane & 7;                   // float4 slot within EMB

    const float4* tab4 = reinterpret_cast<const float4*>(s_tab);
    float4* out4 = reinterpret_cast<float4*>(out) + (size_t)g * 8 + e4;

    // ---- main loop: 32 rows/warp, one row (4 pairs) per iter ----
#pragma unroll 2
    for (int jb = 0; jb < 32; jb++) {
        const float fa = __shfl_sync(0xffffffffu, f0, jb);
        const float fb = __shfl_sync(0xffffffffu, f1, jb);
        const float fc = __shfl_sync(0xffffffffu, f2, jb);
        const float fd = __shfl_sync(0xffffffffu, f3, jb);
        const float fj = (g < 2) ? (g == 0 ? fa : fb)
                                 : (g == 2 ? fc : fd);

        const float xlf = floorf(fj);
        const float wh  = fj - xlf;            // = DELTA*(t-xl), exact
        const float wl  = 1.0f - wh;           // = DELTA*(xh-t)
        const int   bin = (int)xlf + DELTA;    // 0..31

        const float4* p = tab4 + ((bin * A_PER_B + g) << 3) + e4;
        const float4 bl = p[0];
        const float4 bh = p[A_PER_B * 8];      // bin+1: +4 actions * 8 f4

        float4 h;
        h.x = bh.x * wh + bl.x * wl;
        h.y = bh.y * wh + bl.y * wl;
        h.z = bh.z * wh + bl.z * wl;
        h.w = bh.w * wh + bl.w * wl;

        // 32 lanes -> 512B contiguous: (row, a0..a0+3, all EMB)
        __stcs(out4 + ((size_t)(row0 + jb) * ACTIONS + a0) * 8, h);
    }
}

// ---------------------------------------------------------------------------
// Launch: x, bn_weight, bn_bias, emb_table  ->  out [n, ACTIONS, EMB] fp32
// ---------------------------------------------------------------------------
extern "C" void kernel_launch(void* const* d_in, const int* in_sizes, int n_in,
                              void* d_out, int out_size)
{
    const float* x    = (const float*)d_in[0];
    const float* wgt  = (const float*)d_in[1];
    const float* bias = (const float*)d_in[2];
    const float* emb  = (const float*)d_in[3];
    float* out        = (float*)d_out;

    bn_partial<<<NB1, 256>>>(x);

    dim3 grid(N_ROWS / R_PER_B, ACTIONS / A_PER_B);   // (64, 16)
    spline_v4<<<grid, 256>>>(x, emb, wgt, bias, out);
}

// round 14
// speedup vs baseline: 1.5454x; 1.0078x over previous
#include <cuda_runtime.h>
#include <math.h>

#define N_ROWS   16384
#define ACTIONS  64
#define EMB      32
#define DELTA    16
#define EPSF     1e-5f

#define NB1      32                      // bn_partial blocks
#define ROWS_PER_B1 (N_ROWS / NB1)       // 512

#define A_PER_B  4                       // actions per spline block
#define R_PER_B  256                     // rows per spline block
#define NBINS    33                      // staged bins (bl 0..31, bh needs +1)

// Scratch: BN partial sums (no allocation allowed in kernel_launch).
__device__ float g_psum[NB1][ACTIONS];
__device__ float g_psq [NB1][ACTIONS];

// ---------------------------------------------------------------------------
// Kernel 1: per-block partial sum/sumsq per action column. 32 blocks x 512
// rows. float4 loads in explicit 8-deep batches (MLP=8). Deterministic.
// ---------------------------------------------------------------------------
__global__ __launch_bounds__(256) void bn_partial(const float* __restrict__ x)
{
    const int tid = threadIdx.x;
    const int c4  = tid & 15;
    const int r   = tid >> 4;
    const int b   = blockIdx.x;

    const float4* px = reinterpret_cast<const float4*>(x)
                     + (size_t)(b * ROWS_PER_B1 + r) * (ACTIONS / 4) + c4;

    float4 s = {0.f, 0.f, 0.f, 0.f};
    float4 q = {0.f, 0.f, 0.f, 0.f};
#pragma unroll
    for (int m = 0; m < 4; m++) {
        float4 v[8];
#pragma unroll
        for (int k = 0; k < 8; k++)
            v[k] = __ldg(px + (size_t)(m * 8 + k) * 16 * (ACTIONS / 4));
#pragma unroll
        for (int k = 0; k < 8; k++) {
            s.x += v[k].x; q.x += v[k].x * v[k].x;
            s.y += v[k].y; q.y += v[k].y * v[k].y;
            s.z += v[k].z; q.z += v[k].z * v[k].z;
            s.w += v[k].w; q.w += v[k].w * v[k].w;
        }
    }

    __shared__ float4 ss[16][16];
    __shared__ float4 sq[16][16];
    ss[r][c4] = s;
    sq[r][c4] = q;
    __syncthreads();

    if (tid < ACTIONS) {
        const int c = tid, cc = c >> 2, ce = c & 3;
        float ts = 0.f, tq = 0.f;
#pragma unroll
        for (int r2 = 0; r2 < 16; r2++) {
            ts += reinterpret_cast<const float*>(&ss[r2][cc])[ce];
            tq += reinterpret_cast<const float*>(&sq[r2][cc])[ce];
        }
        g_psum[b][c] = ts;
        g_psq [b][c] = tq;
    }
}

// ---------------------------------------------------------------------------
// Kernel 2 (fused): BN prologue + smem-staged spline, v5.
// v4 measured 28.4us = l1tex/MIO bound; per warp-iter the 4 SHFL + 3 SEL of
// the f-broadcast sat on the SAME MIO pipe as LDS/STG dispatch. v5 re-lays
// the per-lane f registers so each iter needs ONE shfl with a compile-time
// register index:
//   lane (g,e4) precomputes F[m] = f(row0+8m+e4, a0+g), m=0..3
//   iter jb=8m+i:  f_j = shfl(F[m], g*8+i)   (F[m] static by full unroll)
// Everything else as v4: 16.9KB staged table (bh = bin+1 row), 2x LDS.128
// conflict-free per warp-iter, one STG.128 of 512B contiguous per warp-iter.
// Full 4x8 unroll lets ptxas batch LDS pairs across iters (hide 29cyc LDS).
// Deterministic: fixed-order butterfly prologue, bit-identical per block.
// ---------------------------------------------------------------------------
__global__ __launch_bounds__(256) void spline_v5(const float* __restrict__ x,
                                                 const float* __restrict__ emb,
                                                 const float* __restrict__ wgt,
                                                 const float* __restrict__ bias,
                                                 float* __restrict__ out)
{
    __shared__ __align__(16) float s_tab[NBINS * A_PER_B * EMB]; // [bin][a][e]
    __shared__ float s_sc[A_PER_B];
    __shared__ float s_sh[A_PER_B];

    const int tid  = threadIdx.x;
    const int lane = tid & 31;
    const int w    = tid >> 5;                 // warp 0..7
    const int a0   = blockIdx.y * A_PER_B;
    const int row0 = blockIdx.x * R_PER_B + w * 32;

    // ---- BN finalize: 4 actions x 32 partials, butterfly reduce ----
    if (tid < 128) {
        const int ai = tid >> 5;
        const int p  = tid & 31;
        float s = g_psum[p][a0 + ai];
        float q = g_psq [p][a0 + ai];
#pragma unroll
        for (int off = 16; off > 0; off >>= 1) {
            s += __shfl_xor_sync(0xffffffffu, s, off);
            q += __shfl_xor_sync(0xffffffffu, q, off);
        }
        if (p == 0) {
            const float inv_n = 1.0f / (float)N_ROWS;
            float mean = s * inv_n;
            float var  = fmaf(-mean, mean, q * inv_n);
            float sc   = wgt[a0 + ai] * rsqrtf(var + EPSF);
            s_sc[ai] = sc;
            s_sh[ai] = fmaf(-mean, sc, bias[a0 + ai]);
        }
    }

    // ---- stage table slice: bins 0..32, this block's 4 actions ----
    {
        float4* st4 = reinterpret_cast<float4*>(s_tab);
        const float4* e4p = reinterpret_cast<const float4*>(emb);
        // 33*4*8 = 1056 float4
        for (int i = tid; i < NBINS * A_PER_B * 8; i += 256) {
            const int bin = i >> 5;            // /32
            const int a   = (i >> 3) & 3;
            const int e4  = i & 7;
            st4[i] = __ldg(e4p + ((size_t)bin * ACTIONS + a0 + a) * 8 + e4);
        }
    }
    __syncthreads();

    const int g  = lane >> 3;                  // pair group 0..3 (action)
    const int e4 = lane & 7;                   // float4 slot within EMB
    const int g8 = g << 3;

    // ---- prologue: 4 scalar x loads + 4 tanh in F-layout ----
    // F[m] = f(row0 + 8m + e4, a0 + g)
    const float sc = s_sc[g];
    const float sh = s_sh[g];
    float F[4];
    {
        const float* xp = x + (size_t)(row0 + e4) * ACTIONS + a0 + g;
        float xv[4];
#pragma unroll
        for (int m = 0; m < 4; m++)
            xv[m] = __ldg(xp + (size_t)m * 8 * ACTIONS);
#pragma unroll
        for (int m = 0; m < 4; m++) {
            float t = tanhf(fmaf(xv[m], sc, sh));
            t = fminf(fmaxf(t, -1.0f + 1e-5f), 1.0f - 1e-5f);
            F[m] = t * (float)DELTA;           // exact pow2 scale
        }
    }

    const float4* tab4 = reinterpret_cast<const float4*>(s_tab);
    float4* out4 = reinterpret_cast<float4*>(out) + (size_t)g8 + e4;

    // ---- main loop: 32 rows/warp, one row (4 pairs) per iter, full unroll ----
#pragma unroll
    for (int m = 0; m < 4; m++) {
#pragma unroll
        for (int i = 0; i < 8; i++) {
            const int jb = m * 8 + i;
            const float fj = __shfl_sync(0xffffffffu, F[m], g8 + i);

            const float xlf = floorf(fj);
            const float wh  = fj - xlf;        // = DELTA*(t-xl), exact
            const float wl  = 1.0f - wh;       // = DELTA*(xh-t)
            const int   bin = (int)xlf + DELTA;    // 0..31

            const float4* p = tab4 + ((bin * A_PER_B + g) << 3) + e4;
            const float4 bl = p[0];
            const float4 bh = p[A_PER_B * 8];  // bin+1: +4 actions * 8 f4

            float4 h;
            h.x = bh.x * wh + bl.x * wl;
            h.y = bh.y * wh + bl.y * wl;
            h.z = bh.z * wh + bl.z * wl;
            h.w = bh.w * wh + bl.w * wl;

            // 32 lanes -> 512B contiguous: (row, a0..a0+3, all EMB)
            __stcs(out4 + ((size_t)(row0 + jb) * ACTIONS + a0) * 8, h);
        }
    }
}

// ---------------------------------------------------------------------------
// Launch: x, bn_weight, bn_bias, emb_table  ->  out [n, ACTIONS, EMB] fp32
// ---------------------------------------------------------------------------
extern "C" void kernel_launch(void* const* d_in, const int* in_sizes, int n_in,
                              void* d_out, int out_size)
{
    const float* x    = (const float*)d_in[0];
    const float* wgt  = (const float*)d_in[1];
    const float* bias = (const float*)d_in[2];
    const float* emb  = (const float*)d_in[3];
    float* out        = (float*)d_out;

    bn_partial<<<NB1, 256>>>(x);

    dim3 grid(N_ROWS / R_PER_B, ACTIONS / A_PER_B);   // (64, 16)
    spline_v5<<<grid, 256>>>(x, emb, wgt, bias, out);
}